// round 2
// baseline (speedup 1.0000x reference)
#include <cuda_runtime.h>
#include <cstdint>

#define NROW 512
#define NCOL 512
#define NRAY 131072
#define NINT 768

// Padded image: logical (row, col) window [-512, 1536) x [-512, 1536),
// image occupies [0,512)x[0,512), zeros elsewhere -> OOB gathers contribute 0
// with no predicates in the hot loop. Geometry (center 255.5, radius 400,
// t in [0,1]) bounds rounded indices to ~[-146, 657], well inside the pad.
#define PAD_OFF 512
#define PAD_DIM 2048

__device__ float g_pad[PAD_DIM * PAD_DIM];

__global__ void zero_pad_kernel() {
    int i = blockIdx.x * blockDim.x + threadIdx.x;   // 1,048,576 threads
    reinterpret_cast<float4*>(g_pad)[i] = make_float4(0.f, 0.f, 0.f, 0.f);
}

__global__ void copy_img_kernel(const float* __restrict__ img) {
    int i = blockIdx.x * blockDim.x + threadIdx.x;   // 262,144 threads
    int r = i >> 9;
    int c = i & 511;
    g_pad[(PAD_OFF + r) * PAD_DIM + (PAD_OFF + c)] = img[i];
}

struct RayConst {
    float i00, i01, i10, i11, b0, b1;
};

// Bit-exact mirror of the reference index chain:
//   x = sx + t*dx            (separate mul, add -- NOT fma)
//   mx = 0.5*(x0+x1) - b0
//   rowf = i00*mx + i01*my   (mul, mul, add)
//   ri = round-half-even(rowf)
__device__ __forceinline__ void seg_accum(
    float x0, float y0, float x1, float y1, float dt,
    const RayConst& K, const float* __restrict__ base, float& acc)
{
    float mx = __fsub_rn(__fmul_rn(0.5f, __fadd_rn(x0, x1)), K.b0);
    float my = __fsub_rn(__fmul_rn(0.5f, __fadd_rn(y0, y1)), K.b1);
    float rowf = __fadd_rn(__fmul_rn(K.i00, mx), __fmul_rn(K.i01, my));
    float colf = __fadd_rn(__fmul_rn(K.i10, mx), __fmul_rn(K.i11, my));
    int ri = __float2int_rn(rowf);   // half-to-even == jnp.round
    int ci = __float2int_rn(colf);
    float pix = __ldg(base + (ptrdiff_t)ri * PAD_DIM + ci);
    acc = fmaf(pix, dt, acc);        // internal accumulation: precision-free
}

__global__ __launch_bounds__(256) void ct_kernel(
    const float* __restrict__ t_sorted,
    const float* __restrict__ Mm,
    const float* __restrict__ bb,
    const float* __restrict__ src,
    const float* __restrict__ dst,
    float* __restrict__ out)
{
    const unsigned full = 0xffffffffu;
    int ray  = (blockIdx.x * blockDim.x + threadIdx.x) >> 5;  // warp per ray
    int lane = threadIdx.x & 31;

    // 2x2 inverse (exact identity for M = I, matching jnp.linalg.inv there)
    float m00 = Mm[0], m01 = Mm[1], m10 = Mm[2], m11 = Mm[3];
    float invdet = 1.0f / (m00 * m11 - m01 * m10);
    RayConst K;
    K.i00 =  m11 * invdet; K.i01 = -m01 * invdet;
    K.i10 = -m10 * invdet; K.i11 =  m00 * invdet;
    K.b0 = bb[0]; K.b1 = bb[1];

    float sx = src[2 * ray],                  sy = src[2 * ray + 1];
    float dx = __fsub_rn(dst[2 * ray], sx);   // matches (dst - src) rounding
    float dy = __fsub_rn(dst[2 * ray + 1], sy);
    float L  = sqrtf(dx * dx + dy * dy);      // one sqrt per ray (len = dt*L)

    const float* base = g_pad + (PAD_OFF * PAD_DIM + PAD_OFF);
    const float4* t4 = reinterpret_cast<const float4*>(
        t_sorted + (size_t)ray * NINT);

    float acc = 0.0f;

    // lane holds t[128c + 4*lane .. +3]; 6 chunks of 128 t-values.
    float4 cur = __ldcs(&t4[lane]);

    #pragma unroll
    for (int c = 0; c < 6; ++c) {
        const bool last = (c == 5);
        float4 nxt = make_float4(0.f, 0.f, 0.f, 0.f);
        if (!last) nxt = __ldcs(&t4[(c + 1) * 32 + lane]);

        float tn = __shfl_down_sync(full, cur.x, 1);   // next lane's first t
        float nf = __shfl_sync(full, nxt.x, 0);        // next chunk's first t
        if (lane == 31) tn = nf;

        // Endpoint coordinates, mirroring reference: x = sx + t*dx (mul, add)
        float x0 = __fadd_rn(sx, __fmul_rn(cur.x, dx));
        float y0 = __fadd_rn(sy, __fmul_rn(cur.x, dy));
        float x1 = __fadd_rn(sx, __fmul_rn(cur.y, dx));
        float y1 = __fadd_rn(sy, __fmul_rn(cur.y, dy));
        float x2 = __fadd_rn(sx, __fmul_rn(cur.z, dx));
        float y2 = __fadd_rn(sy, __fmul_rn(cur.z, dy));
        float x3 = __fadd_rn(sx, __fmul_rn(cur.w, dx));
        float y3 = __fadd_rn(sy, __fmul_rn(cur.w, dy));
        float x4 = __fadd_rn(sx, __fmul_rn(tn, dx));
        float y4 = __fadd_rn(sy, __fmul_rn(tn, dy));

        seg_accum(x0, y0, x1, y1, cur.y - cur.x, K, base, acc);
        seg_accum(x1, y1, x2, y2, cur.z - cur.y, K, base, acc);
        seg_accum(x2, y2, x3, y3, cur.w - cur.z, K, base, acc);
        if (!last || lane != 31)   // last chunk, lane 31: no 4th segment
            seg_accum(x3, y3, x4, y4, tn - cur.w, K, base, acc);

        cur = nxt;
    }

    // warp reduction
    #pragma unroll
    for (int s = 16; s > 0; s >>= 1)
        acc += __shfl_xor_sync(full, acc, s);

    if (lane == 0) out[ray] = acc * L;
}

extern "C" void kernel_launch(void* const* d_in, const int* in_sizes, int n_in,
                              void* d_out, int out_size)
{
    const float* image    = (const float*)d_in[0];
    const float* t_sorted = (const float*)d_in[1];
    const float* M        = (const float*)d_in[2];
    const float* b        = (const float*)d_in[3];
    const float* src      = (const float*)d_in[4];
    const float* dst      = (const float*)d_in[5];
    float* out = (float*)d_out;

    zero_pad_kernel<<<4096, 256>>>();
    copy_img_kernel<<<1024, 256>>>(image);
    ct_kernel<<<NRAY / 8, 256>>>(t_sorted, M, b, src, dst, out);
}

// round 3
// speedup vs baseline: 1.5329x; 1.5329x over previous
#include <cuda_runtime.h>
#include <cstdint>

#define NRAY 131072
#define NINT 768

// Padded images: logical window [-512,1536)^2, image at [0,512)^2, zeros
// elsewhere -> OOB gathers contribute 0 with no predicates. __device__
// globals are zero-initialized at module load and we never write nonzero
// outside the interior, so no per-launch zeroing is needed.
#define PAD_OFF 512
#define PAD_DIM 2048

__device__ float g_pad [PAD_DIM * PAD_DIM];   // [row][col]
__device__ float g_padT[PAD_DIM * PAD_DIM];   // [col][row]

__global__ void copy_img_kernel(const float* __restrict__ img) {
    int i = blockIdx.x * blockDim.x + threadIdx.x;   // 262,144 threads
    int r = i >> 9;
    int c = i & 511;
    float v = img[i];
    g_pad [(PAD_OFF + r) * PAD_DIM + (PAD_OFF + c)] = v;
    g_padT[(PAD_OFF + c) * PAD_DIM + (PAD_OFF + r)] = v;
}

#define MAGICF 12582912.0f              /* 2^23 + 2^22: fadd == rint (RN-even) */
#define CBIAS  (0x4B400000u * 2048u + 0x4B400000u)   /* uint32 wrap, exact */

// Fast path: M == I, b == 0 (verified at runtime). u = slow index (x2048
// stride), v = fast index; (su,du)/(sv,dv) are the pre-swapped coordinate
// sources so the ray's dominant direction is contiguous in `basec`.
__device__ __forceinline__ float ray_loop_ident(
    const float* __restrict__ tp, int lane,
    float su, float du, float sv, float dv,
    const float* __restrict__ basec)
{
    const unsigned full = 0xffffffffu;
    float acc = 0.0f;
    float t0 = __ldcs(tp + lane);

    #pragma unroll 4
    for (int j = 0; j < 24; ++j) {
        float tload = 0.0f;
        if (j < 23) tload = __ldcs(tp + 32 * (j + 1) + lane);
        float tn = __shfl_down_sync(full, t0, 1);
        float tf = __shfl_sync(full, tload, 0);
        if (lane == 31) tn = tf;

        // Bit-exact reference chain (x = s + t*d; mid = 0.5*(x0+x1);
        // M=I, b=0 terms elided -- elisions are exact except ±0 sign,
        // which rounds to the same integer index).
        float xu0 = __fadd_rn(su, __fmul_rn(t0, du));
        float xv0 = __fadd_rn(sv, __fmul_rn(t0, dv));
        float xu1 = __fadd_rn(su, __fmul_rn(tn, du));
        float xv1 = __fadd_rn(sv, __fmul_rn(tn, dv));
        float uf = __fmul_rn(0.5f, __fadd_rn(xu0, xu1));
        float vf = __fmul_rn(0.5f, __fadd_rn(xv0, xv1));

        unsigned ub = __float_as_uint(__fadd_rn(uf, MAGICF));
        unsigned vb = __float_as_uint(__fadd_rn(vf, MAGICF));
        int idx = (int)(ub * 2048u + vb - CBIAS);
        float pix = __ldg(basec + idx);

        if (j < 23 || lane != 31)            // segment 767 doesn't exist
            acc = fmaf(pix, __fsub_rn(tn, t0), acc);
        t0 = tload;
    }
    return acc;
}

// General path: arbitrary M, b. Coefficient rows (cu*, cv*) pre-swapped per
// ray so u is the slow index.
__device__ __forceinline__ float ray_loop_gen(
    const float* __restrict__ tp, int lane,
    float sx, float dx, float sy, float dy, float b0, float b1,
    float cu0, float cu1, float cv0, float cv1,
    const float* __restrict__ basec)
{
    const unsigned full = 0xffffffffu;
    float acc = 0.0f;
    float t0 = __ldcs(tp + lane);

    #pragma unroll 4
    for (int j = 0; j < 24; ++j) {
        float tload = 0.0f;
        if (j < 23) tload = __ldcs(tp + 32 * (j + 1) + lane);
        float tn = __shfl_down_sync(full, t0, 1);
        float tf = __shfl_sync(full, tload, 0);
        if (lane == 31) tn = tf;

        float x0 = __fadd_rn(sx, __fmul_rn(t0, dx));
        float y0 = __fadd_rn(sy, __fmul_rn(t0, dy));
        float x1 = __fadd_rn(sx, __fmul_rn(tn, dx));
        float y1 = __fadd_rn(sy, __fmul_rn(tn, dy));
        float mx = __fsub_rn(__fmul_rn(0.5f, __fadd_rn(x0, x1)), b0);
        float my = __fsub_rn(__fmul_rn(0.5f, __fadd_rn(y0, y1)), b1);
        float uf = __fadd_rn(__fmul_rn(cu0, mx), __fmul_rn(cu1, my));
        float vf = __fadd_rn(__fmul_rn(cv0, mx), __fmul_rn(cv1, my));

        unsigned ub = __float_as_uint(__fadd_rn(uf, MAGICF));
        unsigned vb = __float_as_uint(__fadd_rn(vf, MAGICF));
        int idx = (int)(ub * 2048u + vb - CBIAS);
        float pix = __ldg(basec + idx);

        if (j < 23 || lane != 31)
            acc = fmaf(pix, __fsub_rn(tn, t0), acc);
        t0 = tload;
    }
    return acc;
}

__global__ __launch_bounds__(256) void ct_kernel(
    const float* __restrict__ t_sorted,
    const float* __restrict__ Mm,
    const float* __restrict__ bb,
    const float* __restrict__ src,
    const float* __restrict__ dst,
    float* __restrict__ out)
{
    const unsigned full = 0xffffffffu;
    int ray  = (blockIdx.x * blockDim.x + threadIdx.x) >> 5;   // warp per ray
    int lane = threadIdx.x & 31;

    float m00 = Mm[0], m01 = Mm[1], m10 = Mm[2], m11 = Mm[3];
    float invdet = 1.0f / (m00 * m11 - m01 * m10);
    float i00 =  m11 * invdet, i01 = -m01 * invdet;
    float i10 = -m10 * invdet, i11 =  m00 * invdet;
    float b0 = bb[0], b1 = bb[1];
    bool ident = (i00 == 1.0f) & (i01 == 0.0f) & (i10 == 0.0f) &
                 (i11 == 1.0f) & (b0 == 0.0f) & (b1 == 0.0f);

    float sx = src[2 * ray],                sy = src[2 * ray + 1];
    float dx = __fsub_rn(dst[2 * ray], sx);
    float dy = __fsub_rn(dst[2 * ray + 1], sy);
    float L  = sqrtf(dx * dx + dy * dy);    // one sqrt per ray (len = dt*L)

    // Rate of change of each index per unit t; the faster one should be the
    // contiguous (v) coordinate -> pick normal or transposed image.
    float r_rate = fabsf(i00 * dx + i01 * dy);
    float c_rate = fabsf(i10 * dx + i11 * dy);
    bool trans = (r_rate > c_rate);         // row varies fast -> transposed

    const float* basec =
        (trans ? g_padT : g_pad) + (PAD_OFF * PAD_DIM + PAD_OFF);
    const float* tp = t_sorted + (size_t)ray * NINT;

    float acc;
    if (ident) {
        // u (slow, x2048) source / v (fast) source, per layout choice
        float su = trans ? sy : sx, du = trans ? dy : dx;
        float sv = trans ? sx : sy, dv = trans ? dx : dy;
        acc = ray_loop_ident(tp, lane, su, du, sv, dv, basec);
    } else {
        float cu0 = trans ? i10 : i00, cu1 = trans ? i11 : i01;
        float cv0 = trans ? i00 : i10, cv1 = trans ? i01 : i11;
        acc = ray_loop_gen(tp, lane, sx, dx, sy, dy, b0, b1,
                           cu0, cu1, cv0, cv1, basec);
    }

    #pragma unroll
    for (int s = 16; s > 0; s >>= 1)
        acc += __shfl_xor_sync(full, acc, s);

    if (lane == 0) out[ray] = acc * L;
}

extern "C" void kernel_launch(void* const* d_in, const int* in_sizes, int n_in,
                              void* d_out, int out_size)
{
    const float* image    = (const float*)d_in[0];
    const float* t_sorted = (const float*)d_in[1];
    const float* M        = (const float*)d_in[2];
    const float* b        = (const float*)d_in[3];
    const float* src      = (const float*)d_in[4];
    const float* dst      = (const float*)d_in[5];
    float* out = (float*)d_out;

    copy_img_kernel<<<1024, 256>>>(image);
    ct_kernel<<<NRAY / 8, 256>>>(t_sorted, M, b, src, dst, out);
}

// round 5
// speedup vs baseline: 1.6004x; 1.0441x over previous
#include <cuda_runtime.h>
#include <cstdint>

#define NRAY 131072
#define NINT 768

// Clamped-border images: rounded indices are clamped to [-1, 512]; array row
// r holds logical index r-1, so rows/cols 0 and 513 are the zero border.
// Any OOB midpoint reads a border zero -> contributes 0 (matches reference
// masking). Footprint ~1.06MB per copy (vs 16MB zero-pad) so OOB gathers
// collapse onto a few hot L1 lines. __device__ BSS is zero-initialized and
// the borders are never written.
#define PDIM    514
#define PSTRIDE 516

__device__ float g_img [PDIM * PSTRIDE];   // [row][col]
__device__ float g_imgT[PDIM * PSTRIDE];   // [col][row]

__global__ void copy_img_kernel(const float* __restrict__ img) {
    int i = blockIdx.x * blockDim.x + threadIdx.x;   // 262,144 threads
    int r = i >> 9;
    int c = i & 511;
    float v = img[i];
    g_img [(r + 1) * PSTRIDE + (c + 1)] = v;
    g_imgT[(c + 1) * PSTRIDE + (r + 1)] = v;
}

#define MAGICF 12582912.0f      /* 2^23+2^22: fadd == rint (round-half-even) */
#define UMINB  0x4B3FFFFFu      /* bits of MAGICF + (-1)  -> clamped row 0   */
#define UMAXB  0x4B400200u      /* bits of MAGICF + 512   -> clamped row 513 */
#define KC     (UMINB * (unsigned)PSTRIDE + UMINB)   /* uint32 wrap, exact   */

// Fast path: M == I, b == 0 (runtime-verified). u = slow index (xPSTRIDE),
// v = fast index; sources pre-swapped so the ray's dominant direction is
// contiguous. Index chain mirrors reference op-for-op (mul, add; no fma),
// all scalar __f*_rn intrinsics -- bit-exact vs the reference (proven R3).
__device__ __forceinline__ float ray_loop_ident(
    const float* __restrict__ tp, int lane,
    float su, float du, float sv, float dv,
    const float* __restrict__ base)
{
    const unsigned full = 0xffffffffu;
    float acc = 0.0f;
    float t0 = __ldcs(tp + lane);

    #pragma unroll 4
    for (int j = 0; j < 24; ++j) {
        float tload = 0.0f;
        if (j < 23) tload = __ldcs(tp + 32 * (j + 1) + lane);
        float tn = __shfl_down_sync(full, t0, 1);
        float tf = __shfl_sync(full, tload, 0);
        if (lane == 31) tn = tf;

        float xu0 = __fadd_rn(su, __fmul_rn(t0, du));
        float xv0 = __fadd_rn(sv, __fmul_rn(t0, dv));
        float xu1 = __fadd_rn(su, __fmul_rn(tn, du));
        float xv1 = __fadd_rn(sv, __fmul_rn(tn, dv));
        float uf = __fmul_rn(0.5f, __fadd_rn(xu0, xu1));
        float vf = __fmul_rn(0.5f, __fadd_rn(xv0, xv1));

        unsigned ub = __float_as_uint(__fadd_rn(uf, MAGICF));
        unsigned vb = __float_as_uint(__fadd_rn(vf, MAGICF));
        ub = umin(umax(ub, UMINB), UMAXB);   // clamp index to [-1, 512]
        vb = umin(umax(vb, UMINB), UMAXB);
        float pix = __ldg(base + (int)(ub * (unsigned)PSTRIDE + vb - KC));

        if (j < 23 || lane != 31)            // segment 767 doesn't exist
            acc = fmaf(pix, __fsub_rn(tn, t0), acc);
        t0 = tload;
    }
    return acc;
}

// General path (cold for this dataset): arbitrary M, b; scalar, bit-exact.
__device__ __forceinline__ float ray_loop_gen(
    const float* __restrict__ tp, int lane,
    float sx, float dx, float sy, float dy, float b0, float b1,
    float cu0, float cu1, float cv0, float cv1,
    const float* __restrict__ base)
{
    const unsigned full = 0xffffffffu;
    float acc = 0.0f;
    float t0 = __ldcs(tp + lane);

    #pragma unroll 4
    for (int j = 0; j < 24; ++j) {
        float tload = 0.0f;
        if (j < 23) tload = __ldcs(tp + 32 * (j + 1) + lane);
        float tn = __shfl_down_sync(full, t0, 1);
        float tf = __shfl_sync(full, tload, 0);
        if (lane == 31) tn = tf;

        float x0 = __fadd_rn(sx, __fmul_rn(t0, dx));
        float y0 = __fadd_rn(sy, __fmul_rn(t0, dy));
        float x1 = __fadd_rn(sx, __fmul_rn(tn, dx));
        float y1 = __fadd_rn(sy, __fmul_rn(tn, dy));
        float mx = __fsub_rn(__fmul_rn(0.5f, __fadd_rn(x0, x1)), b0);
        float my = __fsub_rn(__fmul_rn(0.5f, __fadd_rn(y0, y1)), b1);
        float uf = __fadd_rn(__fmul_rn(cu0, mx), __fmul_rn(cu1, my));
        float vf = __fadd_rn(__fmul_rn(cv0, mx), __fmul_rn(cv1, my));

        unsigned ub = __float_as_uint(__fadd_rn(uf, MAGICF));
        unsigned vb = __float_as_uint(__fadd_rn(vf, MAGICF));
        ub = umin(umax(ub, UMINB), UMAXB);
        vb = umin(umax(vb, UMINB), UMAXB);
        float pix = __ldg(base + (int)(ub * (unsigned)PSTRIDE + vb - KC));

        if (j < 23 || lane != 31)
            acc = fmaf(pix, __fsub_rn(tn, t0), acc);
        t0 = tload;
    }
    return acc;
}

__global__ __launch_bounds__(256) void ct_kernel(
    const float* __restrict__ t_sorted,
    const float* __restrict__ Mm,
    const float* __restrict__ bb,
    const float* __restrict__ src,
    const float* __restrict__ dst,
    float* __restrict__ out)
{
    const unsigned full = 0xffffffffu;
    int ray  = (blockIdx.x * blockDim.x + threadIdx.x) >> 5;   // warp per ray
    int lane = threadIdx.x & 31;

    float m00 = Mm[0], m01 = Mm[1], m10 = Mm[2], m11 = Mm[3];
    float invdet = 1.0f / (m00 * m11 - m01 * m10);
    float i00 =  m11 * invdet, i01 = -m01 * invdet;
    float i10 = -m10 * invdet, i11 =  m00 * invdet;
    float b0 = bb[0], b1 = bb[1];
    bool ident = (i00 == 1.0f) & (i01 == 0.0f) & (i10 == 0.0f) &
                 (i11 == 1.0f) & (b0 == 0.0f) & (b1 == 0.0f);

    float sx = src[2 * ray],                sy = src[2 * ray + 1];
    float dx = __fsub_rn(dst[2 * ray], sx);
    float dy = __fsub_rn(dst[2 * ray + 1], sy);
    float L  = sqrtf(dx * dx + dy * dy);    // one sqrt per ray (len = dt*L)

    // Faster-varying index should be the contiguous (v) coordinate.
    float r_rate = fabsf(i00 * dx + i01 * dy);
    float c_rate = fabsf(i10 * dx + i11 * dy);
    bool trans = (r_rate > c_rate);         // row varies fast -> transposed

    const float* base = trans ? g_imgT : g_img;
    const float* tp = t_sorted + (size_t)ray * NINT;

    float acc;
    if (ident) {
        float su = trans ? sy : sx, du = trans ? dy : dx;
        float sv = trans ? sx : sy, dv = trans ? dx : dy;
        acc = ray_loop_ident(tp, lane, su, du, sv, dv, base);
    } else {
        float cu0 = trans ? i10 : i00, cu1 = trans ? i11 : i01;
        float cv0 = trans ? i00 : i10, cv1 = trans ? i01 : i11;
        acc = ray_loop_gen(tp, lane, sx, dx, sy, dy, b0, b1,
                           cu0, cu1, cv0, cv1, base);
    }

    #pragma unroll
    for (int s = 16; s > 0; s >>= 1)
        acc += __shfl_xor_sync(full, acc, s);

    if (lane == 0) out[ray] = acc * L;
}

extern "C" void kernel_launch(void* const* d_in, const int* in_sizes, int n_in,
                              void* d_out, int out_size)
{
    const float* image    = (const float*)d_in[0];
    const float* t_sorted = (const float*)d_in[1];
    const float* M        = (const float*)d_in[2];
    const float* b        = (const float*)d_in[3];
    const float* src      = (const float*)d_in[4];
    const float* dst      = (const float*)d_in[5];
    float* out = (float*)d_out;

    copy_img_kernel<<<1024, 256>>>(image);
    ct_kernel<<<NRAY / 8, 256>>>(t_sorted, M, b, src, dst, out);
}

// round 7
// speedup vs baseline: 1.7318x; 1.0821x over previous
#include <cuda_runtime.h>
#include <cstdint>

#define NRAY 131072
#define NINT 768

// Clamped-border images: rounded indices clamped to [-1, 512]; array row r
// holds logical index r-1, rows/cols 0 and 513 are the zero border, so any
// OOB midpoint reads 0 -> contributes 0 (matches reference masking).
// __device__ BSS is zero-initialized; borders are never written.
#define PDIM    514
#define PSTRIDE 516

__device__ float g_img [PDIM * PSTRIDE];   // [row][col]
__device__ float g_imgT[PDIM * PSTRIDE];   // [col][row]

__global__ void copy_img_kernel(const float* __restrict__ img) {
    int i = blockIdx.x * blockDim.x + threadIdx.x;   // 262,144 threads
    int r = i >> 9;
    int c = i & 511;
    float v = img[i];
    g_img [(r + 1) * PSTRIDE + (c + 1)] = v;
    g_imgT[(c + 1) * PSTRIDE + (r + 1)] = v;
}

#define MAGICF 12582912.0f      /* 2^23+2^22: fadd == rint (round-half-even) */
#define UMINB  0x4B3FFFFFu      /* bits of MAGICF + (-1)  -> clamped row 0   */
#define UMAXB  0x4B400200u      /* bits of MAGICF + 512   -> clamped row 513 */
#define KC     (UMINB * (unsigned)PSTRIDE + UMINB)   /* uint32 wrap, exact   */

// Fast path: M == I, b == 0 (runtime-verified). u = slow index (xPSTRIDE),
// v = fast index, pre-swapped so the dominant direction is contiguous.
// Index chain mirrors the reference op-for-op with scalar __f*_rn (proven
// bit-exact in R3/R5). x1 endpoints arrive by shuffle from lane+1 -- the
// bit-identical value that lane computed as its x0. ALL shuffles execute
// unconditionally (warp-uniform); lane selection happens after.
__device__ __forceinline__ float ray_loop_ident(
    const float* __restrict__ tp, int lane,
    float su, float du, float sv, float dv,
    const float* __restrict__ base)
{
    const unsigned full = 0xffffffffu;
    float acc = 0.0f;

    float buf[4];                       // chunks j..j+3 resident (MLP >= 4)
    #pragma unroll
    for (int k = 0; k < 4; ++k)
        buf[k] = __ldcs(tp + 32 * k + lane);

    #pragma unroll
    for (int j = 0; j < 24; ++j) {
        float t0 = buf[j & 3];
        float tload = 0.0f;
        if (j < 20) tload = __ldcs(tp + 32 * (j + 4) + lane);  // prefetch j+4

        // Warp-uniform shuffles; per-lane select afterwards.
        float tfirst = __shfl_sync(full, buf[(j + 1) & 3], 0); // chunk j+1 t[0]
        float tn     = __shfl_down_sync(full, t0, 1);
        if (lane == 31)
            tn = (j < 23) ? tfirst : t0;   // j==23: dt=0 -> exact 0 contrib

        float xu0 = __fadd_rn(su, __fmul_rn(t0, du));
        float xv0 = __fadd_rn(sv, __fmul_rn(t0, dv));
        float xu1 = __shfl_down_sync(full, xu0, 1);
        float xv1 = __shfl_down_sync(full, xv0, 1);
        if (lane == 31) {                  // boundary endpoint, same formula
            xu1 = __fadd_rn(su, __fmul_rn(tn, du));
            xv1 = __fadd_rn(sv, __fmul_rn(tn, dv));
        }

        float uf = __fmul_rn(0.5f, __fadd_rn(xu0, xu1));
        float vf = __fmul_rn(0.5f, __fadd_rn(xv0, xv1));
        unsigned ub = __float_as_uint(__fadd_rn(uf, MAGICF));
        unsigned vb = __float_as_uint(__fadd_rn(vf, MAGICF));
        ub = umin(umax(ub, UMINB), UMAXB);   // clamp index to [-1, 512]
        vb = umin(umax(vb, UMINB), UMAXB);
        float pix = __ldg(base + (int)(ub * (unsigned)PSTRIDE + vb - KC));

        acc = fmaf(pix, __fsub_rn(tn, t0), acc);
        buf[j & 3] = tload;
    }
    return acc;
}

// General path (cold for this dataset): arbitrary M, b; same structure.
__device__ __forceinline__ float ray_loop_gen(
    const float* __restrict__ tp, int lane,
    float sx, float dx, float sy, float dy, float b0, float b1,
    float cu0, float cu1, float cv0, float cv1,
    const float* __restrict__ base)
{
    const unsigned full = 0xffffffffu;
    float acc = 0.0f;

    float buf[4];
    #pragma unroll
    for (int k = 0; k < 4; ++k)
        buf[k] = __ldcs(tp + 32 * k + lane);

    #pragma unroll
    for (int j = 0; j < 24; ++j) {
        float t0 = buf[j & 3];
        float tload = 0.0f;
        if (j < 20) tload = __ldcs(tp + 32 * (j + 4) + lane);

        float tfirst = __shfl_sync(full, buf[(j + 1) & 3], 0);
        float tn     = __shfl_down_sync(full, t0, 1);
        if (lane == 31)
            tn = (j < 23) ? tfirst : t0;

        float x0 = __fadd_rn(sx, __fmul_rn(t0, dx));
        float y0 = __fadd_rn(sy, __fmul_rn(t0, dy));
        float x1 = __shfl_down_sync(full, x0, 1);
        float y1 = __shfl_down_sync(full, y0, 1);
        if (lane == 31) {
            x1 = __fadd_rn(sx, __fmul_rn(tn, dx));
            y1 = __fadd_rn(sy, __fmul_rn(tn, dy));
        }

        float mx = __fsub_rn(__fmul_rn(0.5f, __fadd_rn(x0, x1)), b0);
        float my = __fsub_rn(__fmul_rn(0.5f, __fadd_rn(y0, y1)), b1);
        float uf = __fadd_rn(__fmul_rn(cu0, mx), __fmul_rn(cu1, my));
        float vf = __fadd_rn(__fmul_rn(cv0, mx), __fmul_rn(cv1, my));

        unsigned ub = __float_as_uint(__fadd_rn(uf, MAGICF));
        unsigned vb = __float_as_uint(__fadd_rn(vf, MAGICF));
        ub = umin(umax(ub, UMINB), UMAXB);
        vb = umin(umax(vb, UMINB), UMAXB);
        float pix = __ldg(base + (int)(ub * (unsigned)PSTRIDE + vb - KC));

        acc = fmaf(pix, __fsub_rn(tn, t0), acc);
        buf[j & 3] = tload;
    }
    return acc;
}

__global__ __launch_bounds__(256) void ct_kernel(
    const float* __restrict__ t_sorted,
    const float* __restrict__ Mm,
    const float* __restrict__ bb,
    const float* __restrict__ src,
    const float* __restrict__ dst,
    float* __restrict__ out)
{
    const unsigned full = 0xffffffffu;
    int ray  = (blockIdx.x * blockDim.x + threadIdx.x) >> 5;   // warp per ray
    int lane = threadIdx.x & 31;

    float m00 = Mm[0], m01 = Mm[1], m10 = Mm[2], m11 = Mm[3];
    float invdet = 1.0f / (m00 * m11 - m01 * m10);
    float i00 =  m11 * invdet, i01 = -m01 * invdet;
    float i10 = -m10 * invdet, i11 =  m00 * invdet;
    float b0 = bb[0], b1 = bb[1];
    bool ident = (i00 == 1.0f) & (i01 == 0.0f) & (i10 == 0.0f) &
                 (i11 == 1.0f) & (b0 == 0.0f) & (b1 == 0.0f);

    float sx = src[2 * ray],                sy = src[2 * ray + 1];
    float dx = __fsub_rn(dst[2 * ray], sx);
    float dy = __fsub_rn(dst[2 * ray + 1], sy);
    float L  = sqrtf(dx * dx + dy * dy);    // one sqrt per ray (len = dt*L)

    // Faster-varying index should be the contiguous (v) coordinate.
    float r_rate = fabsf(i00 * dx + i01 * dy);
    float c_rate = fabsf(i10 * dx + i11 * dy);
    bool trans = (r_rate > c_rate);         // row varies fast -> transposed

    const float* base = trans ? g_imgT : g_img;
    const float* tp = t_sorted + (size_t)ray * NINT;

    float acc;
    if (ident) {
        float su = trans ? sy : sx, du = trans ? dy : dx;
        float sv = trans ? sx : sy, dv = trans ? dx : dy;
        acc = ray_loop_ident(tp, lane, su, du, sv, dv, base);
    } else {
        float cu0 = trans ? i10 : i00, cu1 = trans ? i11 : i01;
        float cv0 = trans ? i00 : i10, cv1 = trans ? i01 : i11;
        acc = ray_loop_gen(tp, lane, sx, dx, sy, dy, b0, b1,
                           cu0, cu1, cv0, cv1, base);
    }

    #pragma unroll
    for (int s = 16; s > 0; s >>= 1)
        acc += __shfl_xor_sync(full, acc, s);

    if (lane == 0) out[ray] = acc * L;
}

extern "C" void kernel_launch(void* const* d_in, const int* in_sizes, int n_in,
                              void* d_out, int out_size)
{
    const float* image    = (const float*)d_in[0];
    const float* t_sorted = (const float*)d_in[1];
    const float* M        = (const float*)d_in[2];
    const float* b        = (const float*)d_in[3];
    const float* src      = (const float*)d_in[4];
    const float* dst      = (const float*)d_in[5];
    float* out = (float*)d_out;

    copy_img_kernel<<<1024, 256>>>(image);
    ct_kernel<<<NRAY / 8, 256>>>(t_sorted, M, b, src, dst, out);
}

// round 8
// speedup vs baseline: 1.7993x; 1.0390x over previous
#include <cuda_runtime.h>
#include <cstdint>

#define NRAY 131072
#define NINT 768

// Clamped-border images: rounded indices clamped to [-1, 512]; array row r
// holds logical index r-1, rows/cols 0 and 513 are the zero border, so any
// OOB midpoint reads 0 -> contributes 0 (matches reference masking).
// __device__ BSS is zero-initialized; borders are never written.
#define PDIM    514
#define PSTRIDE 516

__device__ float g_img [PDIM * PSTRIDE];   // [row][col]
__device__ float g_imgT[PDIM * PSTRIDE];   // [col][row]

__global__ void copy_img_kernel(const float* __restrict__ img) {
    int i = blockIdx.x * blockDim.x + threadIdx.x;   // 262,144 threads
    int r = i >> 9;
    int c = i & 511;
    float v = img[i];
    g_img [(r + 1) * PSTRIDE + (c + 1)] = v;
    g_imgT[(c + 1) * PSTRIDE + (r + 1)] = v;
}

#define MAGICF 12582912.0f      /* 2^23+2^22: fadd == rint (round-half-even) */
#define UMINB  0x4B3FFFFFu      /* bits of MAGICF + (-1)  -> clamped row 0   */
#define UMAXB  0x4B400200u      /* bits of MAGICF + 512   -> clamped row 513 */
#define KC     (UMINB * (unsigned)PSTRIDE + UMINB)   /* uint32 wrap, exact   */

// Fast path: M == I, b == 0 (runtime-verified). u = slow index (xPSTRIDE),
// v = fast index, pre-swapped so the dominant direction is contiguous.
// Index chain mirrors the reference op-for-op with scalar __f*_rn (proven
// bit-exact R3/R5/R7). Endpoints are RECOMPUTED per lane (fma pipe) rather
// than shuffled: SHFL shares the L1tex/LSU pipe with the gathers, which is
// the bottleneck (R7 evidence: L1 65.6%->87.8% when endpoint shuffles were
// added). Only 2 shuffles/iter remain (tn chain).
__device__ __forceinline__ float ray_loop_ident(
    const float* __restrict__ tp, int lane,
    float su, float du, float sv, float dv,
    const float* __restrict__ base)
{
    const unsigned full = 0xffffffffu;
    float acc = 0.0f;

    float buf[4];                       // chunks j..j+3 resident (MLP >= 4)
    #pragma unroll
    for (int k = 0; k < 4; ++k)
        buf[k] = __ldcs(tp + 32 * k + lane);

    #pragma unroll
    for (int j = 0; j < 24; ++j) {
        float t0 = buf[j & 3];
        float tload = 0.0f;
        if (j < 20) tload = __ldcs(tp + 32 * (j + 4) + lane);  // prefetch j+4

        // Warp-uniform shuffles; per-lane select afterwards.
        float tfirst = __shfl_sync(full, buf[(j + 1) & 3], 0); // chunk j+1 t[0]
        float tn     = __shfl_down_sync(full, t0, 1);
        if (lane == 31)
            tn = (j < 23) ? tfirst : t0;   // j==23: dt=0 -> exact 0 contrib

        float xu0 = __fadd_rn(su, __fmul_rn(t0, du));
        float xv0 = __fadd_rn(sv, __fmul_rn(t0, dv));
        float xu1 = __fadd_rn(su, __fmul_rn(tn, du));
        float xv1 = __fadd_rn(sv, __fmul_rn(tn, dv));

        float uf = __fmul_rn(0.5f, __fadd_rn(xu0, xu1));
        float vf = __fmul_rn(0.5f, __fadd_rn(xv0, xv1));
        unsigned ub = __float_as_uint(__fadd_rn(uf, MAGICF));
        unsigned vb = __float_as_uint(__fadd_rn(vf, MAGICF));
        ub = umin(umax(ub, UMINB), UMAXB);   // clamp index to [-1, 512]
        vb = umin(umax(vb, UMINB), UMAXB);
        float pix = __ldg(base + (int)(ub * (unsigned)PSTRIDE + vb - KC));

        acc = fmaf(pix, __fsub_rn(tn, t0), acc);
        buf[j & 3] = tload;
    }
    return acc;
}

// General path (cold for this dataset): arbitrary M, b; same structure.
__device__ __forceinline__ float ray_loop_gen(
    const float* __restrict__ tp, int lane,
    float sx, float dx, float sy, float dy, float b0, float b1,
    float cu0, float cu1, float cv0, float cv1,
    const float* __restrict__ base)
{
    const unsigned full = 0xffffffffu;
    float acc = 0.0f;

    float buf[4];
    #pragma unroll
    for (int k = 0; k < 4; ++k)
        buf[k] = __ldcs(tp + 32 * k + lane);

    #pragma unroll
    for (int j = 0; j < 24; ++j) {
        float t0 = buf[j & 3];
        float tload = 0.0f;
        if (j < 20) tload = __ldcs(tp + 32 * (j + 4) + lane);

        float tfirst = __shfl_sync(full, buf[(j + 1) & 3], 0);
        float tn     = __shfl_down_sync(full, t0, 1);
        if (lane == 31)
            tn = (j < 23) ? tfirst : t0;

        float x0 = __fadd_rn(sx, __fmul_rn(t0, dx));
        float y0 = __fadd_rn(sy, __fmul_rn(t0, dy));
        float x1 = __fadd_rn(sx, __fmul_rn(tn, dx));
        float y1 = __fadd_rn(sy, __fmul_rn(tn, dy));

        float mx = __fsub_rn(__fmul_rn(0.5f, __fadd_rn(x0, x1)), b0);
        float my = __fsub_rn(__fmul_rn(0.5f, __fadd_rn(y0, y1)), b1);
        float uf = __fadd_rn(__fmul_rn(cu0, mx), __fmul_rn(cu1, my));
        float vf = __fadd_rn(__fmul_rn(cv0, mx), __fmul_rn(cv1, my));

        unsigned ub = __float_as_uint(__fadd_rn(uf, MAGICF));
        unsigned vb = __float_as_uint(__fadd_rn(vf, MAGICF));
        ub = umin(umax(ub, UMINB), UMAXB);
        vb = umin(umax(vb, UMINB), UMAXB);
        float pix = __ldg(base + (int)(ub * (unsigned)PSTRIDE + vb - KC));

        acc = fmaf(pix, __fsub_rn(tn, t0), acc);
        buf[j & 3] = tload;
    }
    return acc;
}

__global__ __launch_bounds__(256) void ct_kernel(
    const float* __restrict__ t_sorted,
    const float* __restrict__ Mm,
    const float* __restrict__ bb,
    const float* __restrict__ src,
    const float* __restrict__ dst,
    float* __restrict__ out)
{
    const unsigned full = 0xffffffffu;
    int ray  = (blockIdx.x * blockDim.x + threadIdx.x) >> 5;   // warp per ray
    int lane = threadIdx.x & 31;

    float m00 = Mm[0], m01 = Mm[1], m10 = Mm[2], m11 = Mm[3];
    float invdet = 1.0f / (m00 * m11 - m01 * m10);
    float i00 =  m11 * invdet, i01 = -m01 * invdet;
    float i10 = -m10 * invdet, i11 =  m00 * invdet;
    float b0 = bb[0], b1 = bb[1];
    bool ident = (i00 == 1.0f) & (i01 == 0.0f) & (i10 == 0.0f) &
                 (i11 == 1.0f) & (b0 == 0.0f) & (b1 == 0.0f);

    float sx = src[2 * ray],                sy = src[2 * ray + 1];
    float dx = __fsub_rn(dst[2 * ray], sx);
    float dy = __fsub_rn(dst[2 * ray + 1], sy);
    float L  = sqrtf(dx * dx + dy * dy);    // one sqrt per ray (len = dt*L)

    // Faster-varying index should be the contiguous (v) coordinate.
    float r_rate = fabsf(i00 * dx + i01 * dy);
    float c_rate = fabsf(i10 * dx + i11 * dy);
    bool trans = (r_rate > c_rate);         // row varies fast -> transposed

    const float* base = trans ? g_imgT : g_img;
    const float* tp = t_sorted + (size_t)ray * NINT;

    float acc;
    if (ident) {
        float su = trans ? sy : sx, du = trans ? dy : dx;
        float sv = trans ? sx : sy, dv = trans ? dx : dy;
        acc = ray_loop_ident(tp, lane, su, du, sv, dv, base);
    } else {
        float cu0 = trans ? i10 : i00, cu1 = trans ? i11 : i01;
        float cv0 = trans ? i00 : i10, cv1 = trans ? i01 : i11;
        acc = ray_loop_gen(tp, lane, sx, dx, sy, dy, b0, b1,
                           cu0, cu1, cv0, cv1, base);
    }

    #pragma unroll
    for (int s = 16; s > 0; s >>= 1)
        acc += __shfl_xor_sync(full, acc, s);

    if (lane == 0) out[ray] = acc * L;
}

extern "C" void kernel_launch(void* const* d_in, const int* in_sizes, int n_in,
                              void* d_out, int out_size)
{
    const float* image    = (const float*)d_in[0];
    const float* t_sorted = (const float*)d_in[1];
    const float* M        = (const float*)d_in[2];
    const float* b        = (const float*)d_in[3];
    const float* src      = (const float*)d_in[4];
    const float* dst      = (const float*)d_in[5];
    float* out = (float*)d_out;

    copy_img_kernel<<<1024, 256>>>(image);
    ct_kernel<<<NRAY / 8, 256>>>(t_sorted, M, b, src, dst, out);
}